// round 16
// baseline (speedup 1.0000x reference)
#include <cuda_runtime.h>
#include <cuda_bf16.h>
#include <cuda_fp16.h>
#include <cstdint>

// ---------------------------------------------------------------------------
// Problem constants
// ---------------------------------------------------------------------------
#define NPTS   8192
#define CIN    128
#define DDIM   256
#define KNN    16

#define NODES_PB 4             // nodes per edge-MMA block (M = 4*16 = 64)
#define EM_THREADS 256         // 8 warps: 2 (m) x 4 (n)
#define NCHUNK (NPTS / 2)      // overlap chunking: half the nodes per chunk

// Grid kNN parameters: fat cells so candidate runs are long/contiguous
#define G    16
#define OXC  (-4.0f)
#define CSZ  0.5f
#define NCELL (G * G * G)      // 4096

// Scratch (device globals — no allocation allowed)
__device__ float g_AB[NPTS * 512];
__device__ int   g_idx[NPTS * KNN];
__device__ uint32_t g_W2h32[32768];         // fp16 W2 image, row-major [k][n]
// grid structures
__device__ int    g_hist[NCELL];
__device__ int    g_cstart[NCELL];
__device__ int    g_cptr[NCELL];
__device__ int    g_pcell[NPTS];
__device__ float4 g_spos[NPTS];             // cell-sorted (x,y,z,sq)
__device__ int    g_sid[NPTS];              // sorted -> original index

// ---------------------------------------------------------------------------
// PTX helpers
// ---------------------------------------------------------------------------
__device__ __forceinline__ uint32_t smem_u32(const void* p) {
    uint32_t a;
    asm("{ .reg .u64 t; cvta.to.shared.u64 t, %1; cvt.u32.u64 %0, t; }"
        : "=r"(a) : "l"(p));
    return a;
}
__device__ __forceinline__ void ldsm_x4(uint32_t& r0, uint32_t& r1,
                                        uint32_t& r2, uint32_t& r3, uint32_t addr) {
    asm volatile("ldmatrix.sync.aligned.m8n8.x4.shared.b16 {%0,%1,%2,%3}, [%4];"
                 : "=r"(r0), "=r"(r1), "=r"(r2), "=r"(r3) : "r"(addr));
}
__device__ __forceinline__ void ldsm_x4_t(uint32_t& r0, uint32_t& r1,
                                          uint32_t& r2, uint32_t& r3, uint32_t addr) {
    asm volatile("ldmatrix.sync.aligned.m8n8.x4.trans.shared.b16 {%0,%1,%2,%3}, [%4];"
                 : "=r"(r0), "=r"(r1), "=r"(r2), "=r"(r3) : "r"(addr));
}
__device__ __forceinline__ void mma_f16(float& d0, float& d1, float& d2, float& d3,
                                        uint32_t a0, uint32_t a1, uint32_t a2, uint32_t a3,
                                        uint32_t b0, uint32_t b1) {
    asm volatile("mma.sync.aligned.m16n8k16.row.col.f32.f16.f16.f32 "
                 "{%0,%1,%2,%3}, {%4,%5,%6,%7}, {%8,%9}, {%0,%1,%2,%3};"
                 : "+f"(d0), "+f"(d1), "+f"(d2), "+f"(d3)
                 : "r"(a0), "r"(a1), "r"(a2), "r"(a3), "r"(b0), "r"(b1));
}
__device__ __forceinline__ uint32_t pack_h2(float v0, float v1) {
    return ((uint32_t)__half_as_ushort(__float2half_rn(v1)) << 16) |
           (uint32_t)__half_as_ushort(__float2half_rn(v0));
}
#define CP_ASYNC16(dst, src) \
    asm volatile("cp.async.cg.shared.global [%0], [%1], 16;" \
                 :: "r"(dst), "l"(src) : "memory")
#define CP_ASYNC_COMMIT() asm volatile("cp.async.commit_group;" ::: "memory")
#define CP_ASYNC_WAIT(n)  asm volatile("cp.async.wait_group %0;" :: "n"(n) : "memory")

// ---------------------------------------------------------------------------
// Grid build kernels
// ---------------------------------------------------------------------------
__global__ void __launch_bounds__(1024)
zero_hist_kernel() {
    g_hist[blockIdx.x * 1024 + threadIdx.x] = 0;
}

__global__ void __launch_bounds__(256)
cell_assign_kernel(const float* __restrict__ pos) {
    const int i = blockIdx.x * 256 + threadIdx.x;
    const float x = pos[i * 3 + 0];
    const float y = pos[i * 3 + 1];
    const float z = pos[i * 3 + 2];
    const int cx = min(max(__float2int_rd((x - OXC) * (1.0f / CSZ)), 0), G - 1);
    const int cy = min(max(__float2int_rd((y - OXC) * (1.0f / CSZ)), 0), G - 1);
    const int cz = min(max(__float2int_rd((z - OXC) * (1.0f / CSZ)), 0), G - 1);
    const int c = (cz * G + cy) * G + cx;
    g_pcell[i] = c;
    atomicAdd(&g_hist[c], 1);
}

__global__ void __launch_bounds__(1024)
scan_kernel() {
    __shared__ int sd[1024];
    const int t = threadIdx.x;
    int sum = 0;
#pragma unroll
    for (int k = 0; k < NCELL / 1024; k++) sum += g_hist[t * (NCELL / 1024) + k];
    sd[t] = sum;
    __syncthreads();
    for (int off = 1; off < 1024; off <<= 1) {
        const int v = (t >= off) ? sd[t - off] : 0;
        __syncthreads();
        sd[t] += v;
        __syncthreads();
    }
    int run = sd[t] - sum;
#pragma unroll
    for (int k = 0; k < NCELL / 1024; k++) {
        const int c = t * (NCELL / 1024) + k;
        g_cstart[c] = run;
        g_cptr[c]   = run;
        run += g_hist[c];
    }
}

__global__ void __launch_bounds__(256)
scatter_kernel(const float* __restrict__ pos) {
    const int i = blockIdx.x * 256 + threadIdx.x;
    const int c = g_pcell[i];
    const int dst = atomicAdd(&g_cptr[c], 1);
    const float x = pos[i * 3 + 0];
    const float y = pos[i * 3 + 1];
    const float z = pos[i * 3 + 2];
    const float sq = fmaf(z, z, fmaf(y, y, x * x));
    g_spos[dst] = make_float4(x, y, z, sq);
    g_sid[dst] = i;
}

// ---------------------------------------------------------------------------
// Warp-cooperative exact grid kNN query. One warp per query, chunked by
// sorted position so downstream edge chunks can start as soon as their
// half of the queries is done.
// ---------------------------------------------------------------------------
#define PROCESS_RUN(c0, c1) do {                                               \
    const int _st = g_cstart[(c0)];                                            \
    const int _en = g_cstart[(c1)] + g_hist[(c1)];                             \
    for (int _jb = _st; _jb < _en; _jb += 32) {                                \
        const int _j = _jb + lane;                                             \
        float _dist = 1e30f;                                                   \
        if (_j < _en) {                                                        \
            const float4 _p = g_spos[_j];                                      \
            const float _dot = fmaf(me.z, _p.z, fmaf(me.y, _p.y, me.x * _p.x));\
            _dist = fmaf(-2.0f, _dot, me.w + _p.w);                            \
            if (_j == q) _dist = 1e30f;                                        \
        }                                                                      \
        unsigned _m = __ballot_sync(0xffffffffu, _dist < kth);                 \
        while (_m) {                                                           \
            const int _src = __ffs(_m) - 1; _m &= _m - 1;                      \
            const float _d = __shfl_sync(0xffffffffu, _dist, _src);            \
            if (_d < kth) {                                                    \
                const int _id = _jb + _src;                                    \
                const unsigned _mk =                                           \
                    __ballot_sync(0xffffffffu, bd > _d) & 0xFFFFu;             \
                const int _pos = __ffs(_mk) - 1;   /* nonzero: bd15=kth>_d */  \
                const float _bdu = __shfl_up_sync(0xffffffffu, bd, 1);         \
                const int   _bju = __shfl_up_sync(0xffffffffu, bj, 1);         \
                if (lane >= _pos && lane < KNN) { bd = _bdu; bj = _bju; }      \
                if (lane == _pos) { bd = _d; bj = _id; }                       \
                kth = __shfl_sync(0xffffffffu, bd, KNN - 1);                   \
            }                                                                  \
        }                                                                      \
    }                                                                          \
} while (0)

__global__ void __launch_bounds__(256)
knn_query_kernel(int* __restrict__ idxout, int qbase) {
    const int q    = qbase + ((blockIdx.x * 256 + threadIdx.x) >> 5);
    const int lane = threadIdx.x & 31;

    const float4 me = g_spos[q];
    const int cx = min(max(__float2int_rd((me.x - OXC) * (1.0f / CSZ)), 0), G - 1);
    const int cy = min(max(__float2int_rd((me.y - OXC) * (1.0f / CSZ)), 0), G - 1);
    const int cz = min(max(__float2int_rd((me.z - OXC) * (1.0f / CSZ)), 0), G - 1);

    float bd  = 1e30f;   // lane-distributed sorted list (lanes 0..15)
    int   bj  = -1;
    float kth = 1e30f;   // current 16th-best, warp-uniform

    for (int R = 0; R < G; R++) {
        const int zlo = max(cz - R, 0), zhi = min(cz + R, G - 1);
        const int ylo = max(cy - R, 0), yhi = min(cy + R, G - 1);
        const int xlo = max(cx - R, 0), xhi = min(cx + R, G - 1);
        for (int z = zlo; z <= zhi; z++) {
            const int adz = (z > cz) ? (z - cz) : (cz - z);
            for (int y = ylo; y <= yhi; y++) {
                const int ady = (y > cy) ? (y - cy) : (cy - y);
                const int rowc = (z * G + y) * G;
                if (adz == R || ady == R) {
                    PROCESS_RUN(rowc + xlo, rowc + xhi);   // whole row, contiguous
                } else {
                    if (cx - R >= 0) PROCESS_RUN(rowc + cx - R, rowc + cx - R);
                    if (cx + R < G)  PROCESS_RUN(rowc + cx + R, rowc + cx + R);
                }
            }
        }
        // exact stop bound: distance to faces of the processed region
        const float dxl = (cx - R > 0)     ? (me.x - (OXC + (cx - R) * CSZ))     : 1e30f;
        const float dxr = (cx + R + 1 < G) ? ((OXC + (cx + R + 1) * CSZ) - me.x) : 1e30f;
        const float dyl = (cy - R > 0)     ? (me.y - (OXC + (cy - R) * CSZ))     : 1e30f;
        const float dyr = (cy + R + 1 < G) ? ((OXC + (cy + R + 1) * CSZ) - me.y) : 1e30f;
        const float dzl = (cz - R > 0)     ? (me.z - (OXC + (cz - R) * CSZ))     : 1e30f;
        const float dzr = (cz + R + 1 < G) ? ((OXC + (cz + R + 1) * CSZ) - me.z) : 1e30f;
        const float dmin = fminf(fminf(fminf(dxl, dxr), fminf(dyl, dyr)),
                                 fminf(dzl, dzr));
        if (dmin * dmin >= kth) break;
    }

    if (lane < KNN) {
        const int orig = g_sid[q];
        idxout[orig * KNN + lane] = g_sid[bj];
    }
}

// ---------------------------------------------------------------------------
// Kernel 2: AB = X @ [W1top - W1bot | W1bot], b1 folded into A columns
// ---------------------------------------------------------------------------
__global__ void __launch_bounds__(256)
gemm1_kernel(const float* __restrict__ X,
             const float* __restrict__ W1,
             const float* __restrict__ b1,
             float* __restrict__ AB) {
    __shared__ float As[16][65];
    __shared__ float Bs[16][64];

    const int bm = blockIdx.y * 64;
    const int bn = blockIdx.x * 64;
    const int t  = threadIdx.x;
    const int tx = t & 15;
    const int ty = t >> 4;

    float acc[4][4];
#pragma unroll
    for (int a = 0; a < 4; a++)
#pragma unroll
        for (int b = 0; b < 4; b++) acc[a][b] = 0.0f;

    for (int k0 = 0; k0 < CIN; k0 += 16) {
#pragma unroll
        for (int r = 0; r < 4; r++) {
            const int e = t + r * 256;
            const int m = e >> 4, k = e & 15;
            As[k][m] = X[(bm + m) * CIN + k0 + k];
        }
#pragma unroll
        for (int r = 0; r < 4; r++) {
            const int e = t + r * 256;
            const int k = e >> 6, n = e & 63;
            const int gk = k0 + k, gn = bn + n;
            float v;
            if (gn < 256)
                v = W1[gk * 256 + gn] - W1[(gk + 128) * 256 + gn];
            else
                v = W1[(gk + 128) * 256 + (gn - 256)];
            Bs[k][n] = v;
        }
        __syncthreads();

#pragma unroll
        for (int k = 0; k < 16; k++) {
            float a0 = As[k][ty * 4 + 0];
            float a1 = As[k][ty * 4 + 1];
            float a2 = As[k][ty * 4 + 2];
            float a3 = As[k][ty * 4 + 3];
            float b0 = Bs[k][tx * 4 + 0];
            float c1 = Bs[k][tx * 4 + 1];
            float c2 = Bs[k][tx * 4 + 2];
            float b3 = Bs[k][tx * 4 + 3];
            acc[0][0] = fmaf(a0, b0, acc[0][0]); acc[0][1] = fmaf(a0, c1, acc[0][1]);
            acc[0][2] = fmaf(a0, c2, acc[0][2]); acc[0][3] = fmaf(a0, b3, acc[0][3]);
            acc[1][0] = fmaf(a1, b0, acc[1][0]); acc[1][1] = fmaf(a1, c1, acc[1][1]);
            acc[1][2] = fmaf(a1, c2, acc[1][2]); acc[1][3] = fmaf(a1, b3, acc[1][3]);
            acc[2][0] = fmaf(a2, b0, acc[2][0]); acc[2][1] = fmaf(a2, c1, acc[2][1]);
            acc[2][2] = fmaf(a2, c2, acc[2][2]); acc[2][3] = fmaf(a2, b3, acc[2][3]);
            acc[3][0] = fmaf(a3, b0, acc[3][0]); acc[3][1] = fmaf(a3, c1, acc[3][1]);
            acc[3][2] = fmaf(a3, c2, acc[3][2]); acc[3][3] = fmaf(a3, b3, acc[3][3]);
        }
        __syncthreads();
    }

#pragma unroll
    for (int ii = 0; ii < 4; ii++)
#pragma unroll
        for (int jj = 0; jj < 4; jj++) {
            const int gn = bn + tx * 4 + jj;
            const float bias = (gn < 256) ? b1[gn] : 0.0f;
            AB[(bm + ty * 4 + ii) * 512 + gn] = acc[ii][jj] + bias;
        }
}

// ---------------------------------------------------------------------------
// Kernel 2b: convert W2 into a single fp16 row-major [k][n] image
// ---------------------------------------------------------------------------
__global__ void __launch_bounds__(256)
w2split_kernel(const float* __restrict__ W2) {
    const int id = blockIdx.x * 256 + threadIdx.x;
    const float4 v = ((const float4*)W2)[id];
    g_W2h32[id * 2 + 0] = pack_h2(v.x, v.y);
    g_W2h32[id * 2 + 1] = pack_h2(v.z, v.w);
}

// ---------------------------------------------------------------------------
// Kernel 3: mma.sync fp16 edge GEMM, single-term (A_fp16 * B_fp16).
// Block = 4 nodes addressed by SORTED position (g_sid lookup), M=64,
// 256 threads = 8 warps (2m x 4n), K=256 in 8 chunks of k=32,
// double-buffered cp.async W2 stream. 64KB smem -> 2 CTAs/SM.
// ---------------------------------------------------------------------------
#define SA_HI   0
#define SB_BASE 32768
#define SB_BUF  16384
#define SM_TOTAL 65536

__global__ void __launch_bounds__(EM_THREADS, 2)
edge_mma_kernel(const float* __restrict__ AB,
                const int* __restrict__ idx,
                const float* __restrict__ b2,
                float* __restrict__ out,
                int pbase) {
    extern __shared__ char smem[];
    const uint32_t sbase = smem_u32(smem);
    __shared__ int idxs[64];
    __shared__ int norig[NODES_PB];

    const int t    = threadIdx.x;
    const int lane = t & 31;
    const int wid  = t >> 5;
    const int wm   = wid & 1;        // 2 m-warps (rows 32*wm)
    const int wn   = wid >> 1;       // 4 n-warps (cols 64*wn)
    const int p0   = pbase + blockIdx.x * NODES_PB;   // sorted positions

    if (t < 64) {
        const int orig = g_sid[p0 + (t >> 4)];
        if ((t & 15) == 0) norig[t >> 4] = orig;
        idxs[t] = idx[orig * KNN + (t & 15)];
    }
    __syncthreads();

    // ---- prologue: async-load W2 chunk 0 (overlaps gather phase) ----
    {
#pragma unroll
        for (int ii = 0; ii < 4; ii++) {
            const int e = t + ii * EM_THREADS;       // 0..1023
            const int row = e >> 5, c = e & 31;
            const uint32_t dst = sbase + SB_BASE + row * 512 + ((c ^ (row & 7)) * 16);
            const int src = row * 32 + c;
            CP_ASYNC16(dst, (const uint4*)g_W2h32 + src);
        }
        CP_ASYNC_COMMIT();
    }

    // ---- Phase A: gather + relu + fp16 convert -> smem (rows = edges) ----
    {
        const int r = t >> 2;                // edge row 0..63
        const int q = t & 3;                 // 64-col quarter
        const int j = idxs[r];
        const float4* arow = (const float4*)(AB + (size_t)norig[r >> 4] * 512) + q * 16;
        const float4* brow = (const float4*)(AB + (size_t)j * 512 + 256) + q * 16;
        const int sw_r = r & 7;
        char* smem_c = smem;
#pragma unroll
        for (int w = 0; w < 8; w++) {
            const float4 a0 = arow[w * 2 + 0];
            const float4 a1 = arow[w * 2 + 1];
            const float4 e0 = brow[w * 2 + 0];
            const float4 e1 = brow[w * 2 + 1];
            uint4 H;
            H.x = pack_h2(fmaxf(a0.x + e0.x, 0.0f), fmaxf(a0.y + e0.y, 0.0f));
            H.y = pack_h2(fmaxf(a0.z + e0.z, 0.0f), fmaxf(a0.w + e0.w, 0.0f));
            H.z = pack_h2(fmaxf(a1.x + e1.x, 0.0f), fmaxf(a1.y + e1.y, 0.0f));
            H.w = pack_h2(fmaxf(a1.z + e1.z, 0.0f), fmaxf(a1.w + e1.w, 0.0f));
            const int c = (q * 8 + w) ^ sw_r;
            *(uint4*)(smem_c + SA_HI + r * 512 + c * 16) = H;
        }
    }
    __syncthreads();

    // ---- Main loop: 8 chunks of k=32, double-buffered ----
    float D[2][8][4];
#pragma unroll
    for (int mt = 0; mt < 2; mt++)
#pragma unroll
        for (int f = 0; f < 8; f++)
#pragma unroll
            for (int c = 0; c < 4; c++) D[mt][f][c] = 0.0f;

    const int a_row  = wm * 32 + (lane & 15);
    const int a_swz  = a_row & 7;
    const uint32_t a_base = sbase + SA_HI + a_row * 512;
    const int b_krow  = lane & 15;
    const int b_cbase = wn * 8 + (lane >> 4);

    for (int kc = 0; kc < 8; kc++) {
        if (kc < 7) {
            const int b = (kc + 1) & 1;
#pragma unroll
            for (int ii = 0; ii < 4; ii++) {
                const int e = t + ii * EM_THREADS;
                const int row = e >> 5, c = e & 31;
                const uint32_t dst = sbase + SB_BASE + b * SB_BUF +
                                     row * 512 + ((c ^ (row & 7)) * 16);
                const int src = ((kc + 1) * 32 + row) * 32 + c;
                CP_ASYNC16(dst, (const uint4*)g_W2h32 + src);
            }
            CP_ASYNC_COMMIT();
            CP_ASYNC_WAIT(1);
        } else {
            CP_ASYNC_WAIT(0);
        }
        __syncthreads();

        const uint32_t sb = sbase + SB_BASE + (kc & 1) * SB_BUF;
#pragma unroll
        for (int kt = 0; kt < 2; kt++) {
            const int kg = kc * 2 + kt;
            uint32_t ah[2][4];
#pragma unroll
            for (int mt = 0; mt < 2; mt++) {
                const uint32_t roff = mt * 16 * 512;
                const uint32_t c = (uint32_t)((kg * 2 + (lane >> 4)) ^ a_swz) * 16;
                ldsm_x4(ah[mt][0], ah[mt][1], ah[mt][2], ah[mt][3], a_base + roff + c);
            }
#pragma unroll
            for (int g = 0; g < 4; g++) {
                const int krow = kt * 16 + b_krow;
                const uint32_t c = (uint32_t)((b_cbase + g * 2) ^ (krow & 7)) * 16;
                const uint32_t baddr = sb + krow * 512 + c;
                uint32_t bh0, bh1, bh2, bh3;
                ldsm_x4_t(bh0, bh1, bh2, bh3, baddr);
#pragma unroll
                for (int mt = 0; mt < 2; mt++) {
                    float* d0 = D[mt][g * 2 + 0];
                    float* d1 = D[mt][g * 2 + 1];
                    mma_f16(d0[0], d0[1], d0[2], d0[3],
                            ah[mt][0], ah[mt][1], ah[mt][2], ah[mt][3], bh0, bh1);
                    mma_f16(d1[0], d1[1], d1[2], d1[3],
                            ah[mt][0], ah[mt][1], ah[mt][2], ah[mt][3], bh2, bh3);
                }
            }
        }
        __syncthreads();
    }

    // ---- Epilogue: max over each node's 16 rows (warp-local) + b2 ----
#pragma unroll
    for (int mt = 0; mt < 2; mt++) {
        const int node = norig[wm * 2 + mt];
#pragma unroll
        for (int f = 0; f < 8; f++) {
            float m0 = fmaxf(D[mt][f][0], D[mt][f][2]);
            float m1 = fmaxf(D[mt][f][1], D[mt][f][3]);
            m0 = fmaxf(m0, __shfl_xor_sync(0xffffffffu, m0, 4));
            m1 = fmaxf(m1, __shfl_xor_sync(0xffffffffu, m1, 4));
            m0 = fmaxf(m0, __shfl_xor_sync(0xffffffffu, m0, 8));
            m1 = fmaxf(m1, __shfl_xor_sync(0xffffffffu, m1, 8));
            m0 = fmaxf(m0, __shfl_xor_sync(0xffffffffu, m0, 16));
            m1 = fmaxf(m1, __shfl_xor_sync(0xffffffffu, m1, 16));
            if ((lane >> 2) == 0) {
                const int col = wn * 64 + f * 8 + 2 * (lane & 3);
                float2 o;
                o.x = m0 + b2[col];
                o.y = m1 + b2[col + 1];
                *(float2*)(out + (size_t)node * DDIM + col) = o;
            }
        }
    }
}

// ---------------------------------------------------------------------------
// Launch: 3-stream DAG.
//   s0: build -> knnq(chunk0) -> edge(chunk0)
//   s2: gemm1 + w2split (overlaps build+knnq0)
//   s3: knnq(chunk1) after knnq0 -> edge(chunk1)   (knnq1 overlaps edge0)
// ---------------------------------------------------------------------------
extern "C" void kernel_launch(void* const* d_in, const int* in_sizes, int n_in,
                              void* d_out, int out_size) {
    const float* x   = (const float*)d_in[0];
    const float* pos = (const float*)d_in[1];
    const float* W1  = (const float*)d_in[2];
    const float* b1  = (const float*)d_in[3];
    const float* W2  = (const float*)d_in[4];
    const float* b2  = (const float*)d_in[5];
    float* out = (float*)d_out;
    (void)in_sizes; (void)n_in; (void)out_size;

    int*   idx_ptr = nullptr;
    float* ab_ptr  = nullptr;
    cudaGetSymbolAddress((void**)&idx_ptr, g_idx);
    cudaGetSymbolAddress((void**)&ab_ptr, g_AB);

    static bool init_done = false;
    static cudaStream_t s2 = nullptr, s3 = nullptr;
    static cudaEvent_t ev_fork = nullptr, ev_prep = nullptr;
    static cudaEvent_t ev_k0 = nullptr, ev_e1 = nullptr;
    if (!init_done) {
        cudaGetLastError();
        cudaFuncSetAttribute(edge_mma_kernel,
                             cudaFuncAttributeMaxDynamicSharedMemorySize, SM_TOTAL);
        cudaStreamCreateWithFlags(&s2, cudaStreamNonBlocking);
        cudaStreamCreateWithFlags(&s3, cudaStreamNonBlocking);
        cudaEventCreateWithFlags(&ev_fork, cudaEventDisableTiming);
        cudaEventCreateWithFlags(&ev_prep, cudaEventDisableTiming);
        cudaEventCreateWithFlags(&ev_k0, cudaEventDisableTiming);
        cudaEventCreateWithFlags(&ev_e1, cudaEventDisableTiming);
        init_done = true;
    }

    // fork
    cudaEventRecord(ev_fork, 0);
    cudaStreamWaitEvent(s2, ev_fork, 0);

    // s2: MLP prep (overlaps build + knnq0)
    gemm1_kernel<<<dim3(512 / 64, NPTS / 64), 256, 0, s2>>>(x, W1, b1, ab_ptr);
    w2split_kernel<<<64, 256, 0, s2>>>(W2);
    cudaEventRecord(ev_prep, s2);

    // s0: grid build + first kNN chunk
    zero_hist_kernel<<<NCELL / 1024, 1024>>>();
    cell_assign_kernel<<<NPTS / 256, 256>>>(pos);
    scan_kernel<<<1, 1024>>>();
    scatter_kernel<<<NPTS / 256, 256>>>(pos);
    knn_query_kernel<<<NCHUNK * 32 / 256, 256>>>(idx_ptr, 0);
    cudaEventRecord(ev_k0, 0);

    // s3: second kNN chunk (serialized after chunk0 so chunk0 finishes early;
    // overlaps edge chunk0's tensor work) -> edge chunk1
    cudaStreamWaitEvent(s3, ev_k0, 0);
    knn_query_kernel<<<NCHUNK * 32 / 256, 256, 0, s3>>>(idx_ptr, NCHUNK);
    cudaStreamWaitEvent(s3, ev_prep, 0);
    edge_mma_kernel<<<NCHUNK / NODES_PB, EM_THREADS, SM_TOTAL, s3>>>(
        ab_ptr, idx_ptr, b2, out, NCHUNK);
    cudaEventRecord(ev_e1, s3);

    // s0: edge chunk0 (after knnq0 on-stream, AB via ev_prep)
    cudaStreamWaitEvent(0, ev_prep, 0);
    edge_mma_kernel<<<NCHUNK / NODES_PB, EM_THREADS, SM_TOTAL>>>(
        ab_ptr, idx_ptr, b2, out, 0);

    // join s3 back into the capture-origin stream
    cudaStreamWaitEvent(0, ev_e1, 0);
}

// round 17
// speedup vs baseline: 1.1094x; 1.1094x over previous
#include <cuda_runtime.h>
#include <cuda_bf16.h>
#include <cuda_fp16.h>
#include <cstdint>

// ---------------------------------------------------------------------------
// Problem constants
// ---------------------------------------------------------------------------
#define NPTS   8192
#define CIN    128
#define DDIM   256
#define KNN    16

#define NODES_PB 4             // nodes per edge-MMA block (M = 4*16 = 64)
#define EM_THREADS 256         // 8 warps: 2 (m) x 4 (n)

// Grid kNN parameters: fat cells so candidate runs are long/contiguous
#define G    16
#define OXC  (-4.0f)
#define CSZ  0.5f
#define NCELL (G * G * G)      // 4096

// Scratch (device globals — no allocation allowed)
__device__ float g_AB[NPTS * 512];
__device__ int   g_idx[NPTS * KNN];
__device__ uint32_t g_W2h32[32768];         // fp16 W2 image, row-major [k][n]
// grid structures
__device__ int    g_hist[NCELL];
__device__ int    g_cstart[NCELL];
__device__ float4 g_spos[NPTS];             // cell-sorted (x,y,z,sq)
__device__ int    g_sid[NPTS];              // sorted -> original index

// ---------------------------------------------------------------------------
// PTX helpers
// ---------------------------------------------------------------------------
__device__ __forceinline__ uint32_t smem_u32(const void* p) {
    uint32_t a;
    asm("{ .reg .u64 t; cvta.to.shared.u64 t, %1; cvt.u32.u64 %0, t; }"
        : "=r"(a) : "l"(p));
    return a;
}
__device__ __forceinline__ void ldsm_x4(uint32_t& r0, uint32_t& r1,
                                        uint32_t& r2, uint32_t& r3, uint32_t addr) {
    asm volatile("ldmatrix.sync.aligned.m8n8.x4.shared.b16 {%0,%1,%2,%3}, [%4];"
                 : "=r"(r0), "=r"(r1), "=r"(r2), "=r"(r3) : "r"(addr));
}
__device__ __forceinline__ void ldsm_x4_t(uint32_t& r0, uint32_t& r1,
                                          uint32_t& r2, uint32_t& r3, uint32_t addr) {
    asm volatile("ldmatrix.sync.aligned.m8n8.x4.trans.shared.b16 {%0,%1,%2,%3}, [%4];"
                 : "=r"(r0), "=r"(r1), "=r"(r2), "=r"(r3) : "r"(addr));
}
__device__ __forceinline__ void mma_f16(float& d0, float& d1, float& d2, float& d3,
                                        uint32_t a0, uint32_t a1, uint32_t a2, uint32_t a3,
                                        uint32_t b0, uint32_t b1) {
    asm volatile("mma.sync.aligned.m16n8k16.row.col.f32.f16.f16.f32 "
                 "{%0,%1,%2,%3}, {%4,%5,%6,%7}, {%8,%9}, {%0,%1,%2,%3};"
                 : "+f"(d0), "+f"(d1), "+f"(d2), "+f"(d3)
                 : "r"(a0), "r"(a1), "r"(a2), "r"(a3), "r"(b0), "r"(b1));
}
__device__ __forceinline__ uint32_t pack_h2(float v0, float v1) {
    return ((uint32_t)__half_as_ushort(__float2half_rn(v1)) << 16) |
           (uint32_t)__half_as_ushort(__float2half_rn(v0));
}
#define CP_ASYNC16(dst, src) \
    asm volatile("cp.async.cg.shared.global [%0], [%1], 16;" \
                 :: "r"(dst), "l"(src) : "memory")
#define CP_ASYNC_COMMIT() asm volatile("cp.async.commit_group;" ::: "memory")
#define CP_ASYNC_WAIT(n)  asm volatile("cp.async.wait_group %0;" :: "n"(n) : "memory")

// ---------------------------------------------------------------------------
// Fused grid build: histogram + scan + scatter in ONE single-block kernel.
// 1024 threads, 8 points each. smem: counts 16KB + starts 16KB + scan 4KB.
// ---------------------------------------------------------------------------
__global__ void __launch_bounds__(1024)
grid_build_kernel(const float* __restrict__ pos) {
    __shared__ int sh[NCELL];      // counts, then (unchanged) counts
    __shared__ int ss[NCELL];      // scatter cursors (= starts, bumped)
    __shared__ int sd[1024];       // scan temp
    const int t = threadIdx.x;

    // zero counts
#pragma unroll
    for (int k = 0; k < NCELL / 1024; k++) sh[t + k * 1024] = 0;
    __syncthreads();

    // per-point cell assignment (kept in regs) + smem histogram
    int   cellv[8];
    float px[8], py[8], pz[8];
#pragma unroll
    for (int r = 0; r < 8; r++) {
        const int i = t + r * 1024;
        const float x = pos[i * 3 + 0];
        const float y = pos[i * 3 + 1];
        const float z = pos[i * 3 + 2];
        px[r] = x; py[r] = y; pz[r] = z;
        const int cx = min(max(__float2int_rd((x - OXC) * (1.0f / CSZ)), 0), G - 1);
        const int cy = min(max(__float2int_rd((y - OXC) * (1.0f / CSZ)), 0), G - 1);
        const int cz = min(max(__float2int_rd((z - OXC) * (1.0f / CSZ)), 0), G - 1);
        const int c = (cz * G + cy) * G + cx;
        cellv[r] = c;
        atomicAdd(&sh[c], 1);
    }
    __syncthreads();

    // scan (4 cells per thread + Hillis-Steele over 1024 partials)
    int sum = 0;
#pragma unroll
    for (int k = 0; k < 4; k++) sum += sh[t * 4 + k];
    sd[t] = sum;
    __syncthreads();
    for (int off = 1; off < 1024; off <<= 1) {
        const int v = (t >= off) ? sd[t - off] : 0;
        __syncthreads();
        sd[t] += v;
        __syncthreads();
    }
    int run = sd[t] - sum;
#pragma unroll
    for (int k = 0; k < 4; k++) {
        const int c = t * 4 + k;
        g_hist[c]   = sh[c];
        g_cstart[c] = run;
        ss[c]       = run;
        run += sh[c];
    }
    __syncthreads();

    // scatter into cell-sorted order
#pragma unroll
    for (int r = 0; r < 8; r++) {
        const int i = t + r * 1024;
        const int dst = atomicAdd(&ss[cellv[r]], 1);
        const float x = px[r], y = py[r], z = pz[r];
        g_spos[dst] = make_float4(x, y, z, fmaf(z, z, fmaf(y, y, x * x)));
        g_sid[dst] = i;
    }
}

// ---------------------------------------------------------------------------
// Warp-cooperative exact grid kNN query. One warp per query.
// Lane-distributed sorted top-16 (lanes 0..15), ballot+ffs+shfl_up insertion.
// ---------------------------------------------------------------------------
#define PROCESS_RUN(c0, c1) do {                                               \
    const int _st = g_cstart[(c0)];                                            \
    const int _en = g_cstart[(c1)] + g_hist[(c1)];                             \
    for (int _jb = _st; _jb < _en; _jb += 32) {                                \
        const int _j = _jb + lane;                                             \
        float _dist = 1e30f;                                                   \
        if (_j < _en) {                                                        \
            const float4 _p = g_spos[_j];                                      \
            const float _dot = fmaf(me.z, _p.z, fmaf(me.y, _p.y, me.x * _p.x));\
            _dist = fmaf(-2.0f, _dot, me.w + _p.w);                            \
            if (_j == q) _dist = 1e30f;                                        \
        }                                                                      \
        unsigned _m = __ballot_sync(0xffffffffu, _dist < kth);                 \
        while (_m) {                                                           \
            const int _src = __ffs(_m) - 1; _m &= _m - 1;                      \
            const float _d = __shfl_sync(0xffffffffu, _dist, _src);            \
            if (_d < kth) {                                                    \
                const int _id = _jb + _src;                                    \
                const unsigned _mk =                                           \
                    __ballot_sync(0xffffffffu, bd > _d) & 0xFFFFu;             \
                const int _pos = __ffs(_mk) - 1;   /* nonzero: bd15=kth>_d */  \
                const float _bdu = __shfl_up_sync(0xffffffffu, bd, 1);         \
                const int   _bju = __shfl_up_sync(0xffffffffu, bj, 1);         \
                if (lane >= _pos && lane < KNN) { bd = _bdu; bj = _bju; }      \
                if (lane == _pos) { bd = _d; bj = _id; }                       \
                kth = __shfl_sync(0xffffffffu, bd, KNN - 1);                   \
            }                                                                  \
        }                                                                      \
    }                                                                          \
} while (0)

__global__ void __launch_bounds__(256)
knn_query_kernel(int* __restrict__ idxout) {
    const int q    = (blockIdx.x * 256 + threadIdx.x) >> 5;   // one warp per query
    const int lane = threadIdx.x & 31;

    const float4 me = g_spos[q];
    const int cx = min(max(__float2int_rd((me.x - OXC) * (1.0f / CSZ)), 0), G - 1);
    const int cy = min(max(__float2int_rd((me.y - OXC) * (1.0f / CSZ)), 0), G - 1);
    const int cz = min(max(__float2int_rd((me.z - OXC) * (1.0f / CSZ)), 0), G - 1);

    float bd  = 1e30f;   // lane-distributed sorted list (lanes 0..15)
    int   bj  = -1;
    float kth = 1e30f;   // current 16th-best, warp-uniform

    for (int R = 0; R < G; R++) {
        const int zlo = max(cz - R, 0), zhi = min(cz + R, G - 1);
        const int ylo = max(cy - R, 0), yhi = min(cy + R, G - 1);
        const int xlo = max(cx - R, 0), xhi = min(cx + R, G - 1);
        for (int z = zlo; z <= zhi; z++) {
            const int adz = (z > cz) ? (z - cz) : (cz - z);
            for (int y = ylo; y <= yhi; y++) {
                const int ady = (y > cy) ? (y - cy) : (cy - y);
                const int rowc = (z * G + y) * G;
                if (adz == R || ady == R) {
                    PROCESS_RUN(rowc + xlo, rowc + xhi);   // whole row, contiguous
                } else {
                    if (cx - R >= 0) PROCESS_RUN(rowc + cx - R, rowc + cx - R);
                    if (cx + R < G)  PROCESS_RUN(rowc + cx + R, rowc + cx + R);
                }
            }
        }
        // exact stop bound: distance to faces of the processed region
        const float dxl = (cx - R > 0)     ? (me.x - (OXC + (cx - R) * CSZ))     : 1e30f;
        const float dxr = (cx + R + 1 < G) ? ((OXC + (cx + R + 1) * CSZ) - me.x) : 1e30f;
        const float dyl = (cy - R > 0)     ? (me.y - (OXC + (cy - R) * CSZ))     : 1e30f;
        const float dyr = (cy + R + 1 < G) ? ((OXC + (cy + R + 1) * CSZ) - me.y) : 1e30f;
        const float dzl = (cz - R > 0)     ? (me.z - (OXC + (cz - R) * CSZ))     : 1e30f;
        const float dzr = (cz + R + 1 < G) ? ((OXC + (cz + R + 1) * CSZ) - me.z) : 1e30f;
        const float dmin = fminf(fminf(fminf(dxl, dxr), fminf(dyl, dyr)),
                                 fminf(dzl, dzr));
        if (dmin * dmin >= kth) break;
    }

    if (lane < KNN) {
        const int orig = g_sid[q];
        idxout[orig * KNN + lane] = g_sid[bj];
    }
}

// ---------------------------------------------------------------------------
// Kernel 2: AB = X @ [W1top - W1bot | W1bot], b1 folded into A columns
// ---------------------------------------------------------------------------
__global__ void __launch_bounds__(256)
gemm1_kernel(const float* __restrict__ X,
             const float* __restrict__ W1,
             const float* __restrict__ b1,
             float* __restrict__ AB) {
    __shared__ float As[16][65];
    __shared__ float Bs[16][64];

    const int bm = blockIdx.y * 64;
    const int bn = blockIdx.x * 64;
    const int t  = threadIdx.x;
    const int tx = t & 15;
    const int ty = t >> 4;

    float acc[4][4];
#pragma unroll
    for (int a = 0; a < 4; a++)
#pragma unroll
        for (int b = 0; b < 4; b++) acc[a][b] = 0.0f;

    for (int k0 = 0; k0 < CIN; k0 += 16) {
#pragma unroll
        for (int r = 0; r < 4; r++) {
            const int e = t + r * 256;
            const int m = e >> 4, k = e & 15;
            As[k][m] = X[(bm + m) * CIN + k0 + k];
        }
#pragma unroll
        for (int r = 0; r < 4; r++) {
            const int e = t + r * 256;
            const int k = e >> 6, n = e & 63;
            const int gk = k0 + k, gn = bn + n;
            float v;
            if (gn < 256)
                v = W1[gk * 256 + gn] - W1[(gk + 128) * 256 + gn];
            else
                v = W1[(gk + 128) * 256 + (gn - 256)];
            Bs[k][n] = v;
        }
        __syncthreads();

#pragma unroll
        for (int k = 0; k < 16; k++) {
            float a0 = As[k][ty * 4 + 0];
            float a1 = As[k][ty * 4 + 1];
            float a2 = As[k][ty * 4 + 2];
            float a3 = As[k][ty * 4 + 3];
            float b0 = Bs[k][tx * 4 + 0];
            float c1 = Bs[k][tx * 4 + 1];
            float c2 = Bs[k][tx * 4 + 2];
            float b3 = Bs[k][tx * 4 + 3];
            acc[0][0] = fmaf(a0, b0, acc[0][0]); acc[0][1] = fmaf(a0, c1, acc[0][1]);
            acc[0][2] = fmaf(a0, c2, acc[0][2]); acc[0][3] = fmaf(a0, b3, acc[0][3]);
            acc[1][0] = fmaf(a1, b0, acc[1][0]); acc[1][1] = fmaf(a1, c1, acc[1][1]);
            acc[1][2] = fmaf(a1, c2, acc[1][2]); acc[1][3] = fmaf(a1, b3, acc[1][3]);
            acc[2][0] = fmaf(a2, b0, acc[2][0]); acc[2][1] = fmaf(a2, c1, acc[2][1]);
            acc[2][2] = fmaf(a2, c2, acc[2][2]); acc[2][3] = fmaf(a2, b3, acc[2][3]);
            acc[3][0] = fmaf(a3, b0, acc[3][0]); acc[3][1] = fmaf(a3, c1, acc[3][1]);
            acc[3][2] = fmaf(a3, c2, acc[3][2]); acc[3][3] = fmaf(a3, b3, acc[3][3]);
        }
        __syncthreads();
    }

#pragma unroll
    for (int ii = 0; ii < 4; ii++)
#pragma unroll
        for (int jj = 0; jj < 4; jj++) {
            const int gn = bn + tx * 4 + jj;
            const float bias = (gn < 256) ? b1[gn] : 0.0f;
            AB[(bm + ty * 4 + ii) * 512 + gn] = acc[ii][jj] + bias;
        }
}

// ---------------------------------------------------------------------------
// Kernel 2b: convert W2 into a single fp16 row-major [k][n] image
// ---------------------------------------------------------------------------
__global__ void __launch_bounds__(256)
w2split_kernel(const float* __restrict__ W2) {
    const int id = blockIdx.x * 256 + threadIdx.x;
    const float4 v = ((const float4*)W2)[id];
    g_W2h32[id * 2 + 0] = pack_h2(v.x, v.y);
    g_W2h32[id * 2 + 1] = pack_h2(v.z, v.w);
}

// ---------------------------------------------------------------------------
// Kernel 3: mma.sync fp16 edge GEMM, single-term (A_fp16 * B_fp16).
// Block = 4 nodes (M=64), 256 threads = 8 warps (2m x 4n), K=256 in 8 chunks
// of k=32, double-buffered cp.async W2 stream. 64KB smem -> 2 CTAs/SM.
// (R15-proven monolithic version: i0-based node addressing, single launch)
// ---------------------------------------------------------------------------
#define SA_HI   0
#define SB_BASE 32768
#define SB_BUF  16384          // per buffer: 32 rows x 256 cols fp16
#define SM_TOTAL 65536

__global__ void __launch_bounds__(EM_THREADS, 2)
edge_mma_kernel(const float* __restrict__ AB,
                const int* __restrict__ idx,
                const float* __restrict__ b2,
                float* __restrict__ out) {
    extern __shared__ char smem[];
    const uint32_t sbase = smem_u32(smem);
    __shared__ int idxs[64];

    const int t    = threadIdx.x;
    const int lane = t & 31;
    const int wid  = t >> 5;
    const int wm   = wid & 1;        // 2 m-warps (rows 32*wm)
    const int wn   = wid >> 1;       // 4 n-warps (cols 64*wn)
    const int i0   = blockIdx.x * NODES_PB;

    if (t < 64) idxs[t] = idx[i0 * KNN + t];
    __syncthreads();

    // ---- prologue: async-load W2 chunk 0 (overlaps gather phase) ----
    {
#pragma unroll
        for (int ii = 0; ii < 4; ii++) {
            const int e = t + ii * EM_THREADS;       // 0..1023
            const int row = e >> 5, c = e & 31;
            const uint32_t dst = sbase + SB_BASE + row * 512 + ((c ^ (row & 7)) * 16);
            const int src = row * 32 + c;
            CP_ASYNC16(dst, (const uint4*)g_W2h32 + src);
        }
        CP_ASYNC_COMMIT();
    }

    // ---- Phase A: gather + relu + fp16 convert -> smem (rows = edges) ----
    {
        const int r = t >> 2;                // edge row 0..63
        const int q = t & 3;                 // 64-col quarter
        const int j = idxs[r];
        const float4* arow = (const float4*)(AB + (size_t)(i0 + (r >> 4)) * 512) + q * 16;
        const float4* brow = (const float4*)(AB + (size_t)j * 512 + 256) + q * 16;
        const int sw_r = r & 7;
        char* smem_c = smem;
#pragma unroll
        for (int w = 0; w < 8; w++) {
            const float4 a0 = arow[w * 2 + 0];
            const float4 a1 = arow[w * 2 + 1];
            const float4 e0 = brow[w * 2 + 0];
            const float4 e1 = brow[w * 2 + 1];
            uint4 H;
            H.x = pack_h2(fmaxf(a0.x + e0.x, 0.0f), fmaxf(a0.y + e0.y, 0.0f));
            H.y = pack_h2(fmaxf(a0.z + e0.z, 0.0f), fmaxf(a0.w + e0.w, 0.0f));
            H.z = pack_h2(fmaxf(a1.x + e1.x, 0.0f), fmaxf(a1.y + e1.y, 0.0f));
            H.w = pack_h2(fmaxf(a1.z + e1.z, 0.0f), fmaxf(a1.w + e1.w, 0.0f));
            const int c = (q * 8 + w) ^ sw_r;
            *(uint4*)(smem_c + SA_HI + r * 512 + c * 16) = H;
        }
    }
    __syncthreads();

    // ---- Main loop: 8 chunks of k=32, double-buffered ----
    float D[2][8][4];
#pragma unroll
    for (int mt = 0; mt < 2; mt++)
#pragma unroll
        for (int f = 0; f < 8; f++)
#pragma unroll
            for (int c = 0; c < 4; c++) D[mt][f][c] = 0.0f;

    const int a_row  = wm * 32 + (lane & 15);
    const int a_swz  = a_row & 7;
    const uint32_t a_base = sbase + SA_HI + a_row * 512;
    const int b_krow  = lane & 15;
    const int b_cbase = wn * 8 + (lane >> 4);

    for (int kc = 0; kc < 8; kc++) {
        if (kc < 7) {
            const int b = (kc + 1) & 1;
#pragma unroll
            for (int ii = 0; ii < 4; ii++) {
                const int e = t + ii * EM_THREADS;
                const int row = e >> 5, c = e & 31;
                const uint32_t dst = sbase + SB_BASE + b * SB_BUF +
                                     row * 512 + ((c ^ (row & 7)) * 16);
                const int src = ((kc + 1) * 32 + row) * 32 + c;
                CP_ASYNC16(dst, (const uint4*)g_W2h32 + src);
            }
            CP_ASYNC_COMMIT();
            CP_ASYNC_WAIT(1);
        } else {
            CP_ASYNC_WAIT(0);
        }
        __syncthreads();

        const uint32_t sb = sbase + SB_BASE + (kc & 1) * SB_BUF;
#pragma unroll
        for (int kt = 0; kt < 2; kt++) {
            const int kg = kc * 2 + kt;
            uint32_t ah[2][4];
#pragma unroll
            for (int mt = 0; mt < 2; mt++) {
                const uint32_t roff = mt * 16 * 512;
                const uint32_t c = (uint32_t)((kg * 2 + (lane >> 4)) ^ a_swz) * 16;
                ldsm_x4(ah[mt][0], ah[mt][1], ah[mt][2], ah[mt][3], a_base + roff + c);
            }
#pragma unroll
            for (int g = 0; g < 4; g++) {
                const int krow = kt * 16 + b_krow;
                const uint32_t c = (uint32_t)((b_cbase + g * 2) ^ (krow & 7)) * 16;
                const uint32_t baddr = sb + krow * 512 + c;
                uint32_t bh0, bh1, bh2, bh3;
                ldsm_x4_t(bh0, bh1, bh2, bh3, baddr);
#pragma unroll
                for (int mt = 0; mt < 2; mt++) {
                    float* d0 = D[mt][g * 2 + 0];
                    float* d1 = D[mt][g * 2 + 1];
                    mma_f16(d0[0], d0[1], d0[2], d0[3],
                            ah[mt][0], ah[mt][1], ah[mt][2], ah[mt][3], bh0, bh1);
                    mma_f16(d1[0], d1[1], d1[2], d1[3],
                            ah[mt][0], ah[mt][1], ah[mt][2], ah[mt][3], bh2, bh3);
                }
            }
        }
        __syncthreads();
    }

    // ---- Epilogue: max over each node's 16 rows (warp-local) + b2 ----
#pragma unroll
    for (int mt = 0; mt < 2; mt++) {
        const int node = i0 + wm * 2 + mt;
#pragma unroll
        for (int f = 0; f < 8; f++) {
            float m0 = fmaxf(D[mt][f][0], D[mt][f][2]);
            float m1 = fmaxf(D[mt][f][1], D[mt][f][3]);
            m0 = fmaxf(m0, __shfl_xor_sync(0xffffffffu, m0, 4));
            m1 = fmaxf(m1, __shfl_xor_sync(0xffffffffu, m1, 4));
            m0 = fmaxf(m0, __shfl_xor_sync(0xffffffffu, m0, 8));
            m1 = fmaxf(m1, __shfl_xor_sync(0xffffffffu, m1, 8));
            m0 = fmaxf(m0, __shfl_xor_sync(0xffffffffu, m0, 16));
            m1 = fmaxf(m1, __shfl_xor_sync(0xffffffffu, m1, 16));
            if ((lane >> 2) == 0) {
                const int col = wn * 64 + f * 8 + 2 * (lane & 3);
                float2 o;
                o.x = m0 + b2[col];
                o.y = m1 + b2[col + 1];
                *(float2*)(out + (size_t)node * DDIM + col) = o;
            }
        }
    }
}

// ---------------------------------------------------------------------------
// Launch (R15-proven structure): fork gemm1/w2split onto a side stream so
// they overlap the kNN chain; single monolithic edge launch.
// ---------------------------------------------------------------------------
extern "C" void kernel_launch(void* const* d_in, const int* in_sizes, int n_in,
                              void* d_out, int out_size) {
    const float* x   = (const float*)d_in[0];
    const float* pos = (const float*)d_in[1];
    const float* W1  = (const float*)d_in[2];
    const float* b1  = (const float*)d_in[3];
    const float* W2  = (const float*)d_in[4];
    const float* b2  = (const float*)d_in[5];
    float* out = (float*)d_out;
    (void)in_sizes; (void)n_in; (void)out_size;

    int*   idx_ptr = nullptr;
    float* ab_ptr  = nullptr;
    cudaGetSymbolAddress((void**)&idx_ptr, g_idx);
    cudaGetSymbolAddress((void**)&ab_ptr, g_AB);

    static bool init_done = false;
    static cudaStream_t s2 = nullptr;
    static cudaEvent_t ev_fork = nullptr, ev_join = nullptr;
    if (!init_done) {
        cudaGetLastError();
        cudaFuncSetAttribute(edge_mma_kernel,
                             cudaFuncAttributeMaxDynamicSharedMemorySize, SM_TOTAL);
        cudaStreamCreateWithFlags(&s2, cudaStreamNonBlocking);
        cudaEventCreateWithFlags(&ev_fork, cudaEventDisableTiming);
        cudaEventCreateWithFlags(&ev_join, cudaEventDisableTiming);
        init_done = true;
    }

    // fork: side stream runs gemm1 + w2split concurrently with kNN chain
    cudaEventRecord(ev_fork, 0);
    cudaStreamWaitEvent(s2, ev_fork, 0);

    // main stream: fused grid build + warp-cooperative query
    grid_build_kernel<<<1, 1024>>>(pos);
    knn_query_kernel<<<NPTS * 32 / 256, 256>>>(idx_ptr);

    // side stream: MLP prep
    gemm1_kernel<<<dim3(512 / 64, NPTS / 64), 256, 0, s2>>>(x, W1, b1, ab_ptr);
    w2split_kernel<<<64, 256, 0, s2>>>(W2);
    cudaEventRecord(ev_join, s2);

    // join, then fused edge GEMM
    cudaStreamWaitEvent(0, ev_join, 0);
    edge_mma_kernel<<<NPTS / NODES_PB, EM_THREADS, SM_TOTAL>>>(ab_ptr, idx_ptr, b2, out);
}